// round 14
// baseline (speedup 1.0000x reference)
#include <cuda_runtime.h>
#include <math.h>
#include <stdint.h>

#define B_    64
#define LC_   512
#define LPV_  16
#define LTP_  16
#define V_    8192
#define H_    1024
#define SLEN  545
#define NLOGIT 8736
#define PREF_ 16
#define NEGF  (-1000000000.0f)
#define SCALE_ 0.03125f
#define TAUF  0.67f

typedef unsigned long long u64;

// ---------------- scratch ----------------
__device__ float g_src [B_*SLEN*H_];
__device__ float g_k   [B_*SLEN*H_];
__device__ float g_v   [B_*SLEN*H_];
__device__ float g_mask[B_*SLEN];
__device__ int   g_tctx[B_*LC_];
__device__ float g_emb [B_*H_];
__device__ float g_q   [B_*H_];
__device__ float g_ec  [B_*H_];
__device__ float g_dec [B_*H_];
__device__ float g_sc  [B_*SLEN];
__device__ float g_logits[B_*NLOGIT];
__device__ float g_part[4*1024*1024];

// ---------------- packed f32x2 helpers ----------------
__device__ __forceinline__ void ffma2(u64& d, u64 a, u64 b) {
    asm("fma.rn.f32x2 %0, %1, %2, %0;" : "+l"(d) : "l"(a), "l"(b));
}
__device__ __forceinline__ u64 swap64(u64 x) { return (x >> 32) | (x << 32); }
__device__ __forceinline__ float lo_f(u64 x) { return __uint_as_float((uint32_t)x); }
__device__ __forceinline__ float hi_f(u64 x) { return __uint_as_float((uint32_t)(x >> 32)); }

// ---------------- threefry2x32 (exact JAX semantics) ----------------
__host__ __device__ __forceinline__ void tf2x32(uint32_t k0, uint32_t k1,
                                                uint32_t x0, uint32_t x1,
                                                uint32_t& o0, uint32_t& o1) {
    uint32_t k2 = k0 ^ k1 ^ 0x1BD11BDAu;
#define RND_(r) { x0 += x1; x1 = (x1 << r) | (x1 >> (32 - r)); x1 ^= x0; }
    x0 += k0; x1 += k1;
    RND_(13) RND_(15) RND_(26) RND_(6)   x0 += k1; x1 += k2 + 1u;
    RND_(17) RND_(29) RND_(16) RND_(24)  x0 += k2; x1 += k0 + 2u;
    RND_(13) RND_(15) RND_(26) RND_(6)   x0 += k0; x1 += k1 + 3u;
    RND_(17) RND_(29) RND_(16) RND_(24)  x0 += k1; x1 += k2 + 4u;
    RND_(13) RND_(15) RND_(26) RND_(6)   x0 += k2; x1 += k0 + 5u;
#undef RND_
    o0 = x0; o1 = x1;
}

__device__ __forceinline__ float gumbel_from_bits(uint32_t w) {
    float f = __uint_as_float((w >> 9) | 0x3f800000u) - 1.0f;
    float u = fmaxf(1e-10f, f + 1e-10f);
    return -logf(-logf(u));
}

// ---------------- setup kernels ----------------
__global__ void k_build_src(const int* __restrict__ context, const int* __restrict__ ctxlen,
                            const float* __restrict__ tp_hidden, const float* __restrict__ ar_hidden,
                            const float* __restrict__ E_ctx) {
    int idx = blockIdx.x * 256 + threadIdx.x;
    int h = idx & (H_ - 1);
    int r = idx >> 10;
    int j = r % SLEN;
    int b = r / SLEN;
    float val;
    if (j < LC_) {
        val = (j < ctxlen[b]) ? E_ctx[(long long)context[b*LC_ + j] * H_ + h] : 0.0f;
    } else if (j < LC_ + LPV_) {
        return;  // filled by k_reduce_pv
    } else if (j < LC_ + LPV_ + LTP_) {
        val = tp_hidden[((long long)b*LTP_ + (j - (LC_+LPV_)))*H_ + h];
    } else {
        val = ar_hidden[b*H_ + h];
    }
    g_src[idx] = val;
}

__global__ void k_mask(const int* __restrict__ ctxlen, const float* __restrict__ pvmask,
                       const int* __restrict__ tplen, const int* __restrict__ arlen) {
    int i = blockIdx.x * 256 + threadIdx.x;
    if (i >= B_*SLEN) return;
    int b = i / SLEN, j = i % SLEN;
    float m;
    if (j < LC_)                m = (j < ctxlen[b]) ? 1.0f : 0.0f;
    else if (j < LC_+LPV_)      m = pvmask[b*LPV_ + (j - LC_)];
    else if (j < LC_+LPV_+LTP_) m = ((j - (LC_+LPV_)) < tplen[b]) ? 1.0f : 0.0f;
    else                        m = (0 < arlen[b]) ? 1.0f : 0.0f;
    g_mask[i] = m;
}

__global__ void k_tctx(const int* __restrict__ context, const int* __restrict__ glo2loc) {
    int i = blockIdx.x * 256 + threadIdx.x;
    if (i >= B_*LC_) return;
    g_tctx[i] = glo2loc[context[i]];
}

// ---------------- 128x128 GEMM, f32x2 packed, split-K + masked-tile skip ----------------
__global__ void __launch_bounds__(256) gemm_big(
    const float* __restrict__ A, int lda,
    const float* __restrict__ Bm, int ldb,
    float* __restrict__ Cp, int M, int N, int Kc,
    const int* __restrict__ skip_ctxlen)
{
    __shared__ float As[16][128];
    __shared__ float Bs[16][128];
    int m0 = blockIdx.y * 128, n0 = blockIdx.x * 128;
    int z = blockIdx.z;
    float* C = Cp + (long long)z * M * N;
    int tid = threadIdx.x;

    if (skip_ctxlen) {
        int last = m0 + 127;
        int b0 = m0 / SLEN, b1 = last / SLEN;
        if (b0 == b1) {
            int jl = m0 - b0*SLEN, jr = last - b0*SLEN;
            if (jr < LC_ && jl >= skip_ctxlen[b0]) {
                for (int i = tid; i < 128*128; i += 256) {
                    int r = i >> 7, c = i & 127;
                    if (m0 + r < M) C[(long long)(m0+r)*N + n0 + c] = 0.0f;
                }
                return;
            }
        }
    }

    int k0 = z * Kc;
    int ty = tid >> 4, tx = tid & 15;
    // diag/anti-diag packed accumulators: rows ty*8+2p(+1), cols tx*8+2q(+1)
    u64 accD[4][4], accA[4][4];
    #pragma unroll
    for (int p = 0; p < 4; p++)
        #pragma unroll
        for (int q = 0; q < 4; q++) { accD[p][q] = 0ull; accA[p][q] = 0ull; }

    for (int kt = 0; kt < Kc; kt += 16) {
        #pragma unroll
        for (int i = 0; i < 2; i++) {
            int idx = tid + i*256;
            int r = idx >> 2, c4 = idx & 3;
            float4 av = make_float4(0.f,0.f,0.f,0.f);
            if (m0 + r < M)
                av = *(const float4*)&A[(long long)(m0+r)*lda + k0 + kt + c4*4];
            As[c4*4+0][r] = av.x; As[c4*4+1][r] = av.y;
            As[c4*4+2][r] = av.z; As[c4*4+3][r] = av.w;
        }
        #pragma unroll
        for (int i = 0; i < 2; i++) {
            int idx = tid + i*256;
            int r = idx >> 5, c4 = idx & 31;
            *(float4*)&Bs[r][c4*4] =
                *(const float4*)&Bm[(long long)(k0 + kt + r)*ldb + n0 + c4*4];
        }
        __syncthreads();
        #pragma unroll
        for (int kk = 0; kk < 16; kk++) {
            ulonglong2 aA = *(const ulonglong2*)&As[kk][ty*8];
            ulonglong2 aB = *(const ulonglong2*)&As[kk][ty*8 + 4];
            ulonglong2 bA = *(const ulonglong2*)&Bs[kk][tx*8];
            ulonglong2 bB = *(const ulonglong2*)&Bs[kk][tx*8 + 4];
            u64 ap[4] = {aA.x, aA.y, aB.x, aB.y};
            u64 bp[4] = {bA.x, bA.y, bB.x, bB.y};
            u64 bs[4];
            #pragma unroll
            for (int q = 0; q < 4; q++) bs[q] = swap64(bp[q]);
            #pragma unroll
            for (int p = 0; p < 4; p++)
                #pragma unroll
                for (int q = 0; q < 4; q++) {
                    ffma2(accD[p][q], ap[p], bp[q]);   // (a2p*b2q, a2p+1*b2q+1)
                    ffma2(accA[p][q], ap[p], bs[q]);   // (a2p*b2q+1, a2p+1*b2q)
                }
        }
        __syncthreads();
    }
    #pragma unroll
    for (int p = 0; p < 4; p++) {
        float r0[8], r1[8];
        #pragma unroll
        for (int q = 0; q < 4; q++) {
            r0[2*q]   = lo_f(accD[p][q]); r0[2*q+1] = lo_f(accA[p][q]);
            r1[2*q]   = hi_f(accA[p][q]); r1[2*q+1] = hi_f(accD[p][q]);
        }
        int m = m0 + ty*8 + 2*p;
        if (m < M) {
            *(float4*)&C[(long long)m*N + n0 + tx*8]     = *(float4*)&r0[0];
            *(float4*)&C[(long long)m*N + n0 + tx*8 + 4] = *(float4*)&r0[4];
        }
        if (m + 1 < M) {
            *(float4*)&C[(long long)(m+1)*N + n0 + tx*8]     = *(float4*)&r1[0];
            *(float4*)&C[(long long)(m+1)*N + n0 + tx*8 + 4] = *(float4*)&r1[4];
        }
    }
}

// ---------------- M=64 split-K GEMM (64x64 tile), f32x2 packed ----------------
__global__ void __launch_bounds__(256) gemm_skm(
    const float* __restrict__ A, int lda,
    const float* __restrict__ Bm, int ldb,
    float* __restrict__ part, int N, int Kc)
{
    __shared__ float As[16][64];
    __shared__ float Bs[16][64];
    int n0 = blockIdx.x * 64;
    int z = blockIdx.z;
    int k0 = z * Kc;
    int tid = threadIdx.x;
    int ty = tid >> 4, tx = tid & 15;
    u64 accD[2][2], accA[2][2];
    #pragma unroll
    for (int p = 0; p < 2; p++)
        #pragma unroll
        for (int q = 0; q < 2; q++) { accD[p][q] = 0ull; accA[p][q] = 0ull; }

    for (int kt = 0; kt < Kc; kt += 16) {
        {
            int r = tid >> 2, c4 = tid & 3;
            float4 av = *(const float4*)&A[(long long)r*lda + k0 + kt + c4*4];
            As[c4*4+0][r] = av.x; As[c4*4+1][r] = av.y;
            As[c4*4+2][r] = av.z; As[c4*4+3][r] = av.w;
        }
        {
            int r = tid >> 4, c4 = tid & 15;
            *(float4*)&Bs[r][c4*4] =
                *(const float4*)&Bm[(long long)(k0 + kt + r)*ldb + n0 + c4*4];
        }
        __syncthreads();
        #pragma unroll
        for (int kk = 0; kk < 16; kk++) {
            ulonglong2 av = *(const ulonglong2*)&As[kk][ty*4];
            ulonglong2 bv = *(const ulonglong2*)&Bs[kk][tx*4];
            u64 ap[2] = {av.x, av.y};
            u64 bp[2] = {bv.x, bv.y};
            u64 bs2[2] = {swap64(bv.x), swap64(bv.y)};
            #pragma unroll
            for (int p = 0; p < 2; p++)
                #pragma unroll
                for (int q = 0; q < 2; q++) {
                    ffma2(accD[p][q], ap[p], bp[q]);
                    ffma2(accA[p][q], ap[p], bs2[q]);
                }
        }
        __syncthreads();
    }
    float* C = part + (long long)z * 64 * N;
    #pragma unroll
    for (int p = 0; p < 2; p++) {
        float r0[4], r1[4];
        #pragma unroll
        for (int q = 0; q < 2; q++) {
            r0[2*q]   = lo_f(accD[p][q]); r0[2*q+1] = lo_f(accA[p][q]);
            r1[2*q]   = hi_f(accA[p][q]); r1[2*q+1] = hi_f(accD[p][q]);
        }
        int m = ty*4 + 2*p;
        *(float4*)&C[(long long)m*N + n0 + tx*4]     = *(float4*)&r0[0];
        *(float4*)&C[(long long)(m+1)*N + n0 + tx*4] = *(float4*)&r1[0];
    }
}

// ---------------- reductions ----------------
__global__ void k_reduce_plain(const float* __restrict__ part, float* __restrict__ out,
                               int MN, int S) {
    int i = blockIdx.x*256 + threadIdx.x;
    if (i >= MN) return;
    float s = 0.f;
    for (int z = 0; z < S; z++) s += part[(long long)z*MN + i];
    out[i] = s;
}
__global__ void k_reduce_tanh(const float* __restrict__ part, float* __restrict__ out,
                              int MN, int S) {
    int i = blockIdx.x*256 + threadIdx.x;
    if (i >= MN) return;
    float s = 0.f;
    for (int z = 0; z < S; z++) s += part[(long long)z*MN + i];
    out[i] = tanhf(s);
}
__global__ void k_reduce_gen(const float* __restrict__ part, const float* __restrict__ bias,
                             int S) {
    int i = blockIdx.x*256 + threadIdx.x;
    if (i >= B_*V_) return;
    int m = i >> 13, n = i & (V_ - 1);
    float s = 0.f;
    const int MN = B_*V_;
    for (int z = 0; z < S; z++) s += part[(long long)z*MN + i];
    g_logits[m*NLOGIT + n] = (s + bias[n]) * SCALE_;
}
__global__ void k_reduce_pv(const float* __restrict__ part) {
    int i = blockIdx.x*256 + threadIdx.x;
    if (i >= 1024*H_) return;
    int m = i >> 10, n = i & (H_ - 1);
    float s = 0.f;
    const int MN = 1024*H_;
    #pragma unroll
    for (int z = 0; z < 4; z++) s += part[(long long)z*MN + i];
    int b = m / LPV_, l = m % LPV_;
    g_src[((long long)b*SLEN + LC_ + l)*H_ + n] = s;
}

// ---------------- dot products (mask early-exit) ----------------
__global__ void k_dots(const float* __restrict__ Q, const float* __restrict__ Kr,
                       float* __restrict__ out, int J, int out_stride, int out_off, int mode) {
    int w = threadIdx.x >> 5, lane = threadIdx.x & 31;
    int j = blockIdx.x * 8 + w;
    int b = blockIdx.y;
    if (j >= J) return;
    float m = g_mask[b*SLEN + j];
    if (m == 0.f) {
        if (lane == 0)
            out[(long long)b*out_stride + out_off + j] = (mode == 0) ? NEGF : NEGF * SCALE_;
        return;
    }
    const float4* q4 = (const float4*)(Q + b*H_);
    const float4* k4 = (const float4*)(Kr + ((long long)b*SLEN + j)*H_);
    float s = 0.f;
    #pragma unroll
    for (int i = 0; i < 8; i++) {
        float4 qa = q4[lane + i*32];
        float4 ka = k4[lane + i*32];
        s += qa.x*ka.x + qa.y*ka.y + qa.z*ka.z + qa.w*ka.w;
    }
    #pragma unroll
    for (int o = 16; o; o >>= 1) s += __shfl_xor_sync(0xffffffffu, s, o);
    if (lane == 0)
        out[(long long)b*out_stride + out_off + j] = s * SCALE_;
}

// ---------------- row softmax ----------------
__device__ __forceinline__ float warp_red_max(float v) {
    #pragma unroll
    for (int o = 16; o; o >>= 1) v = fmaxf(v, __shfl_xor_sync(0xffffffffu, v, o));
    return v;
}
__device__ __forceinline__ float warp_red_sum(float v) {
    #pragma unroll
    for (int o = 16; o; o >>= 1) v += __shfl_xor_sync(0xffffffffu, v, o);
    return v;
}
__global__ void k_softmax(const float* __restrict__ in, long long irs,
                          float* __restrict__ out, long long ors, int n) {
    int row = blockIdx.x, tid = threadIdx.x, T = blockDim.x;
    const float* x = in + (long long)row * irs;
    float* y = out + (long long)row * ors;
    __shared__ float sh[32];
    __shared__ float stat[2];
    int lane = tid & 31, wid = tid >> 5, nw = T >> 5;

    float m = -INFINITY;
    for (int i = tid; i < n; i += T) m = fmaxf(m, x[i]);
    m = warp_red_max(m);
    if (lane == 0) sh[wid] = m;
    __syncthreads();
    if (wid == 0) {
        float vv = (lane < nw) ? sh[lane] : -INFINITY;
        vv = warp_red_max(vv);
        if (lane == 0) stat[0] = vv;
    }
    __syncthreads();
    m = stat[0];

    float s = 0.f;
    for (int i = tid; i < n; i += T) s += expf(x[i] - m);
    s = warp_red_sum(s);
    __syncthreads();
    if (lane == 0) sh[wid] = s;
    __syncthreads();
    if (wid == 0) {
        float vv = (lane < nw) ? sh[lane] : 0.f;
        vv = warp_red_sum(vv);
        if (lane == 0) stat[1] = vv;
    }
    __syncthreads();
    float inv = 1.0f / stat[1];
    for (int i = tid; i < n; i += T) y[i] = expf(x[i] - m) * inv;
}

// ---------------- per-step misc ----------------
__global__ void k_emb0(const float* __restrict__ E_topic) {
    int i = blockIdx.x*256 + threadIdx.x;
    g_emb[i] = E_topic[2*H_ + (i & (H_ - 1))];   // BOS = 2
}
// ctx = a @ v, fused with ec = emb + ctx; a==0 rows (masked) skipped
__global__ void k_ctx() {
    __shared__ float sa[SLEN];
    int b = blockIdx.y;
    int h = blockIdx.x*128 + threadIdx.x;
    for (int i = threadIdx.x; i < SLEN; i += 128) sa[i] = g_sc[b*SLEN + i];
    __syncthreads();
    const float* vb = g_v + (long long)b*SLEN*H_ + h;
    float acc = 0.f;
    for (int j = 0; j < SLEN; j++) {
        float aj = sa[j];
        if (aj != 0.f) acc += aj * vb[(long long)j*H_];
    }
    g_ec[b*H_ + h] = g_emb[b*H_ + h] + acc;
}
__global__ void k_buildp(const float* __restrict__ pv_m, float* __restrict__ out1, int t) {
    int b = blockIdx.y;
    int v = blockIdx.x*256 + threadIdx.x;
    __shared__ float pv[16];
    if (threadIdx.x < 16) pv[threadIdx.x] = g_logits[b*NLOGIT + V_ + LC_ + threadIdx.x];
    __syncthreads();
    float p = g_logits[b*NLOGIT + v];
    const float* pvb = pv_m + (long long)b*LPV_*V_ + v;
    #pragma unroll
    for (int l = 0; l < 16; l++) p += pv[l] * pvb[(long long)l*V_];
    out1[(long long)b*PREF_*V_ + (long long)t*V_ + v] = p;
}
__global__ void k_scatter(const int* __restrict__ tp_path, float* __restrict__ out1, int t) {
    int b = blockIdx.x;
    int tid = threadIdx.x;
    float* dst = out1 + (long long)b*PREF_*V_ + (long long)t*V_;
    const float* pr = g_logits + b*NLOGIT;
    if (tid < 16) atomicAdd(&dst[tp_path[b*LTP_ + tid]], pr[V_ + LC_ + LPV_ + tid]);
    for (int l = tid; l < LC_; l += blockDim.x)
        atomicAdd(&dst[g_tctx[b*LC_ + l]], pr[V_ + l]);
}
// Fused gumbel + softmax over V (partitionable threefry: bits = o0^o1 of tf(key,(0,i)))
__global__ void __launch_bounds__(1024) k_gumbel_softmax(
    const float* __restrict__ out1, float* __restrict__ out2,
    int t, uint32_t kk0, uint32_t kk1)
{
    int b = blockIdx.x, tid = threadIdx.x;
    const float* p = out1 + (long long)b*PREF_*V_ + (long long)t*V_;
    float z[8];
    float m = -INFINITY;
    #pragma unroll
    for (int r = 0; r < 8; r++) {
        int v = tid + r*1024;
        uint32_t o0, o1;
        tf2x32(kk0, kk1, 0u, (uint32_t)((b << 13) + v), o0, o1);
        float zz = (logf(p[v] + 1e-10f) + gumbel_from_bits(o0 ^ o1)) / TAUF;
        z[r] = zz; m = fmaxf(m, zz);
    }
    __shared__ float sh[32];
    __shared__ float stat;
    int lane = tid & 31, wid = tid >> 5;
    m = warp_red_max(m);
    if (lane == 0) sh[wid] = m;
    __syncthreads();
    if (wid == 0) {
        float vv = warp_red_max(sh[lane]);
        if (lane == 0) stat = vv;
    }
    __syncthreads();
    m = stat;
    float s = 0.f;
    #pragma unroll
    for (int r = 0; r < 8; r++) { z[r] = expf(z[r] - m); s += z[r]; }
    s = warp_red_sum(s);
    __syncthreads();
    if (lane == 0) sh[wid] = s;
    __syncthreads();
    if (wid == 0) {
        float vv = warp_red_sum(sh[lane]);
        if (lane == 0) stat = vv;
    }
    __syncthreads();
    float inv = 1.0f / stat;
    float* y = out2 + (long long)b*PREF_*V_ + (long long)t*V_;
    #pragma unroll
    for (int r = 0; r < 8; r++) y[tid + r*1024] = z[r] * inv;
}

// ---------------- host orchestration ----------------
extern "C" void kernel_launch(void* const* d_in, const int* in_sizes, int n_in,
                              void* d_out, int out_size) {
    const int*   context     = (const int*)  d_in[0];
    const int*   context_len = (const int*)  d_in[1];
    const float* pv_m        = (const float*)d_in[2];
    const float* pv_m_mask   = (const float*)d_in[3];
    const int*   ar_gth_len  = (const int*)  d_in[5];
    const int*   tp_path     = (const int*)  d_in[6];
    const int*   tp_path_len = (const int*)  d_in[7];
    const float* tp_hidden   = (const float*)d_in[8];
    const float* ar_hidden   = (const float*)d_in[9];
    const float* E_ctx       = (const float*)d_in[10];
    const float* W_p         = (const float*)d_in[11];
    const float* E_topic     = (const float*)d_in[12];
    const float* W_q         = (const float*)d_in[13];
    const float* W_k         = (const float*)d_in[14];
    const float* W_v         = (const float*)d_in[15];
    const float* W_o         = (const float*)d_in[16];
    const float* gen_W       = (const float*)d_in[17];
    const float* gen_b       = (const float*)d_in[18];
    const int*   glo2loc     = (const int*)  d_in[19];

    float* out1 = (float*)d_out;                       // seq_gen_prob (B,16,V)
    float* out2 = out1 + (long long)B_*PREF_*V_;       // seq[:,1:]    (B,16,V)

    float *d_src, *d_k, *d_v, *d_part, *d_emb, *d_q, *d_ec, *d_dec, *d_sc, *d_logits;
    cudaGetSymbolAddress((void**)&d_src,    g_src);
    cudaGetSymbolAddress((void**)&d_k,      g_k);
    cudaGetSymbolAddress((void**)&d_v,      g_v);
    cudaGetSymbolAddress((void**)&d_part,   g_part);
    cudaGetSymbolAddress((void**)&d_emb,    g_emb);
    cudaGetSymbolAddress((void**)&d_q,      g_q);
    cudaGetSymbolAddress((void**)&d_ec,     g_ec);
    cudaGetSymbolAddress((void**)&d_dec,    g_dec);
    cudaGetSymbolAddress((void**)&d_sc,     g_sc);
    cudaGetSymbolAddress((void**)&d_logits, g_logits);

    const int M_src = B_*SLEN;           // 34880

    // ---- precompute ----
    k_build_src<<<(B_*SLEN*H_)/256, 256>>>(context, context_len, tp_hidden, ar_hidden, E_ctx);
    k_mask<<<(B_*SLEN + 255)/256, 256>>>(context_len, pv_m_mask, tp_path_len, ar_gth_len);
    k_tctx<<<(B_*LC_)/256, 256>>>(context, glo2loc);

    // pv_hidden = pv_m (1024x8192) @ W_p (8192x1024), split-K=4
    gemm_big<<<dim3(8, 8, 4), 256>>>(pv_m, V_, W_p, H_, d_part, 1024, H_, V_/4, nullptr);
    k_reduce_pv<<<(1024*H_)/256, 256>>>(d_part);

    // k, v = src @ W_k / W_v  (34880x1024x1024), masked-tile skip
    gemm_big<<<dim3(8, (M_src + 127)/128, 1), 256>>>(d_src, H_, W_k, H_, d_k, M_src, H_, H_, context_len);
    gemm_big<<<dim3(8, (M_src + 127)/128, 1), 256>>>(d_src, H_, W_v, H_, d_v, M_src, H_, H_, context_len);

    // ---- autoregressive steps ----
    for (int t = 0; t < PREF_; t++) {
        // emb
        if (t == 0) {
            k_emb0<<<(B_*H_)/256, 256>>>(E_topic);
        } else {
            gemm_skm<<<dim3(H_/64, 1, 16), 256>>>(out2 + (long long)(t-1)*V_, PREF_*V_,
                                                  E_topic, H_, d_part, H_, V_/16);
            k_reduce_plain<<<(B_*H_)/256, 256>>>(d_part, d_emb, B_*H_, 16);
        }
        // q = emb @ W_q
        gemm_skm<<<dim3(H_/64, 1, 8), 256>>>(d_emb, H_, W_q, H_, d_part, H_, H_/8);
        k_reduce_plain<<<(B_*H_)/256, 256>>>(d_part, d_q, B_*H_, 8);
        // attention scores + softmax
        k_dots<<<dim3((SLEN + 7)/8, B_), 256>>>(d_q, d_k, d_sc, SLEN, SLEN, 0, 0);
        k_softmax<<<B_, 256>>>(d_sc, SLEN, d_sc, SLEN, SLEN);
        // ec = emb + a @ v
        k_ctx<<<dim3(H_/128, B_), 128>>>();
        // dec = tanh(ec @ W_o)
        gemm_skm<<<dim3(H_/64, 1, 8), 256>>>(d_ec, H_, W_o, H_, d_part, H_, H_/8);
        k_reduce_tanh<<<(B_*H_)/256, 256>>>(d_part, d_dec, B_*H_, 8);
        // gen logits
        gemm_skm<<<dim3(V_/64, 1, 2), 256>>>(d_dec, H_, gen_W, V_, d_part, V_, H_/2);
        k_reduce_gen<<<(B_*V_)/256, 256>>>(d_part, gen_b, 2);
        // copy logits
        k_dots<<<dim3((SLEN-1 + 7)/8, B_), 256>>>(d_dec, d_src, d_logits, SLEN-1, NLOGIT, V_, 1);
        // softmax over 8736
        k_softmax<<<B_, 512>>>(d_logits, NLOGIT, d_logits, NLOGIT, NLOGIT);
        // p = gen + pv mixture, then scatter tp/ctx
        k_buildp<<<dim3(V_/256, B_), 256>>>(pv_m, out1, t);
        k_scatter<<<B_, 256>>>(tp_path, out1, t);
        // gumbel + y softmax (fused)
        uint32_t kk0, kk1;
        tf2x32(0u, 42u, 0u, (uint32_t)t, kk0, kk1);
        k_gumbel_softmax<<<B_, 1024>>>(out1, out2, t, kk0, kk1);
    }
    (void)in_sizes; (void)n_in; (void)out_size;
}

// round 15
// speedup vs baseline: 1.0974x; 1.0974x over previous
#include <cuda_runtime.h>
#include <math.h>
#include <stdint.h>

#define B_    64
#define LC_   512
#define LPV_  16
#define LTP_  16
#define V_    8192
#define H_    1024
#define SLEN  545
#define NLOGIT 8736
#define PREF_ 16
#define NEGF  (-1000000000.0f)
#define SCALE_ 0.03125f
#define TAUF  0.67f

// ---------------- scratch ----------------
__device__ float g_src [B_*SLEN*H_];
__device__ float g_k   [B_*SLEN*H_];
__device__ float g_v   [B_*SLEN*H_];
__device__ float g_mask[B_*SLEN];
__device__ int   g_tctx[B_*LC_];
__device__ float g_emb [B_*H_];
__device__ float g_q   [B_*H_];
__device__ float g_ec  [B_*H_];
__device__ float g_dec [B_*H_];
__device__ float g_sc  [B_*SLEN];
__device__ float g_logits[B_*NLOGIT];
__device__ float g_part[4*1024*1024];
__device__ int   g_rowmap[B_*SLEN + 128];
__device__ int   g_live;

// ---------------- threefry2x32 (exact JAX semantics) ----------------
__host__ __device__ __forceinline__ void tf2x32(uint32_t k0, uint32_t k1,
                                                uint32_t x0, uint32_t x1,
                                                uint32_t& o0, uint32_t& o1) {
    uint32_t k2 = k0 ^ k1 ^ 0x1BD11BDAu;
#define RND_(r) { x0 += x1; x1 = (x1 << r) | (x1 >> (32 - r)); x1 ^= x0; }
    x0 += k0; x1 += k1;
    RND_(13) RND_(15) RND_(26) RND_(6)   x0 += k1; x1 += k2 + 1u;
    RND_(17) RND_(29) RND_(16) RND_(24)  x0 += k2; x1 += k0 + 2u;
    RND_(13) RND_(15) RND_(26) RND_(6)   x0 += k0; x1 += k1 + 3u;
    RND_(17) RND_(29) RND_(16) RND_(24)  x0 += k1; x1 += k2 + 4u;
    RND_(13) RND_(15) RND_(26) RND_(6)   x0 += k2; x1 += k0 + 5u;
#undef RND_
    o0 = x0; o1 = x1;
}

__device__ __forceinline__ float gumbel_from_bits(uint32_t w) {
    float f = __uint_as_float((w >> 9) | 0x3f800000u) - 1.0f;
    float u = fmaxf(1e-10f, f + 1e-10f);
    return -logf(-logf(u));
}

// ---------------- setup kernels ----------------
__global__ void k_build_src(const int* __restrict__ context, const int* __restrict__ ctxlen,
                            const float* __restrict__ tp_hidden, const float* __restrict__ ar_hidden,
                            const float* __restrict__ E_ctx) {
    int idx = blockIdx.x * 256 + threadIdx.x;
    int h = idx & (H_ - 1);
    int r = idx >> 10;
    int j = r % SLEN;
    int b = r / SLEN;
    float val;
    if (j < LC_) {
        val = (j < ctxlen[b]) ? E_ctx[(long long)context[b*LC_ + j] * H_ + h] : 0.0f;
    } else if (j < LC_ + LPV_) {
        return;  // filled by k_reduce_pv
    } else if (j < LC_ + LPV_ + LTP_) {
        val = tp_hidden[((long long)b*LTP_ + (j - (LC_+LPV_)))*H_ + h];
    } else {
        val = ar_hidden[b*H_ + h];
    }
    g_src[idx] = val;
}

__global__ void k_mask(const int* __restrict__ ctxlen, const float* __restrict__ pvmask,
                       const int* __restrict__ tplen, const int* __restrict__ arlen) {
    int i = blockIdx.x * 256 + threadIdx.x;
    if (i >= B_*SLEN) return;
    int b = i / SLEN, j = i % SLEN;
    float m;
    if (j < LC_)                m = (j < ctxlen[b]) ? 1.0f : 0.0f;
    else if (j < LC_+LPV_)      m = pvmask[b*LPV_ + (j - LC_)];
    else if (j < LC_+LPV_+LTP_) m = ((j - (LC_+LPV_)) < tplen[b]) ? 1.0f : 0.0f;
    else                        m = (0 < arlen[b]) ? 1.0f : 0.0f;
    g_mask[i] = m;
}

__global__ void k_tctx(const int* __restrict__ context, const int* __restrict__ glo2loc) {
    int i = blockIdx.x * 256 + threadIdx.x;
    if (i >= B_*LC_) return;
    g_tctx[i] = glo2loc[context[i]];
}

// Build compact row map: all ctx-live rows + the [LC_, SLEN) tail of every batch.
__global__ void k_rowmap(const int* __restrict__ ctxlen) {
    __shared__ int offs[65];
    int tid = threadIdx.x;
    if (tid == 0) {
        int acc = 0;
        for (int i = 0; i < 64; i++) { offs[i] = acc; acc += ctxlen[i] + (SLEN - LC_); }
        offs[64] = acc;
    }
    __syncthreads();
    int b = tid;
    int o = offs[b], c = ctxlen[b];
    for (int j = 0; j < c; j++)            g_rowmap[o + j] = b*SLEN + j;
    for (int j = 0; j < SLEN - LC_; j++)   g_rowmap[o + c + j] = b*SLEN + LC_ + j;
    __syncthreads();
    if (tid == 0) {
        int L = offs[64];
        int P = (L + 127) & ~127;
        for (int i = L; i < P; i++) g_rowmap[i] = 0;
        g_live = L;
    }
}

// ---------------- 128x128 GEMM (dense, split-K) ----------------
__global__ void __launch_bounds__(256) gemm_big(
    const float* __restrict__ A, int lda,
    const float* __restrict__ Bm, int ldb,
    float* __restrict__ Cp, int M, int N, int Kc)
{
    __shared__ float As[16][128];
    __shared__ float Bs[16][128];
    int m0 = blockIdx.y * 128, n0 = blockIdx.x * 128;
    int z = blockIdx.z;
    float* C = Cp + (long long)z * M * N;
    int tid = threadIdx.x;
    int k0 = z * Kc;
    int ty = tid >> 4, tx = tid & 15;
    float acc[8][8];
    #pragma unroll
    for (int i = 0; i < 8; i++)
        #pragma unroll
        for (int j = 0; j < 8; j++) acc[i][j] = 0.0f;

    for (int kt = 0; kt < Kc; kt += 16) {
        #pragma unroll
        for (int i = 0; i < 2; i++) {
            int idx = tid + i*256;
            int r = idx >> 2, c4 = idx & 3;
            float4 av = make_float4(0.f,0.f,0.f,0.f);
            if (m0 + r < M)
                av = *(const float4*)&A[(long long)(m0+r)*lda + k0 + kt + c4*4];
            As[c4*4+0][r] = av.x; As[c4*4+1][r] = av.y;
            As[c4*4+2][r] = av.z; As[c4*4+3][r] = av.w;
        }
        #pragma unroll
        for (int i = 0; i < 2; i++) {
            int idx = tid + i*256;
            int r = idx >> 5, c4 = idx & 31;
            *(float4*)&Bs[r][c4*4] =
                *(const float4*)&Bm[(long long)(k0 + kt + r)*ldb + n0 + c4*4];
        }
        __syncthreads();
        #pragma unroll
        for (int kk = 0; kk < 16; kk++) {
            float a[8], b[8];
            *(float4*)&a[0] = *(float4*)&As[kk][ty*8];
            *(float4*)&a[4] = *(float4*)&As[kk][ty*8+4];
            *(float4*)&b[0] = *(float4*)&Bs[kk][tx*8];
            *(float4*)&b[4] = *(float4*)&Bs[kk][tx*8+4];
            #pragma unroll
            for (int i = 0; i < 8; i++)
                #pragma unroll
                for (int j = 0; j < 8; j++)
                    acc[i][j] += a[i] * b[j];
        }
        __syncthreads();
    }
    #pragma unroll
    for (int i = 0; i < 8; i++) {
        int m = m0 + ty*8 + i;
        if (m < M) {
            float4 v0 = make_float4(acc[i][0], acc[i][1], acc[i][2], acc[i][3]);
            float4 v1 = make_float4(acc[i][4], acc[i][5], acc[i][6], acc[i][7]);
            *(float4*)&C[(long long)m*N + n0 + tx*8]     = v0;
            *(float4*)&C[(long long)m*N + n0 + tx*8 + 4] = v1;
        }
    }
}

// ---------------- 128x128 GEMM over compacted live rows (gather/scatter) ----------------
__global__ void __launch_bounds__(256) gemm_gather(
    const float* __restrict__ A,       // g_src, lda = H_
    const float* __restrict__ Bm,      // weight H_ x H_
    float* __restrict__ C)             // output at original row layout, ld = H_
{
    __shared__ float As[16][128];
    __shared__ float Bs[16][128];
    int live = g_live;
    int m0 = blockIdx.y * 128;
    if (m0 >= live) return;
    int n0 = blockIdx.x * 128;
    int tid = threadIdx.x;
    int ty = tid >> 4, tx = tid & 15;

    // per-thread A-row gather indices (2 rows for loading)
    int lr0 = tid >> 2,       lc0 = tid & 3;
    int lr1 = (tid + 256) >> 2, lc1 = (tid + 256) & 3;
    const float* arow0 = A + (long long)g_rowmap[m0 + lr0]*H_;
    const float* arow1 = A + (long long)g_rowmap[m0 + lr1]*H_;

    float acc[8][8];
    #pragma unroll
    for (int i = 0; i < 8; i++)
        #pragma unroll
        for (int j = 0; j < 8; j++) acc[i][j] = 0.0f;

    for (int kt = 0; kt < H_; kt += 16) {
        {
            float4 av = *(const float4*)&arow0[kt + lc0*4];
            As[lc0*4+0][lr0] = av.x; As[lc0*4+1][lr0] = av.y;
            As[lc0*4+2][lr0] = av.z; As[lc0*4+3][lr0] = av.w;
            float4 av1 = *(const float4*)&arow1[kt + lc1*4];
            As[lc1*4+0][lr1] = av1.x; As[lc1*4+1][lr1] = av1.y;
            As[lc1*4+2][lr1] = av1.z; As[lc1*4+3][lr1] = av1.w;
        }
        #pragma unroll
        for (int i = 0; i < 2; i++) {
            int idx = tid + i*256;
            int r = idx >> 5, c4 = idx & 31;
            *(float4*)&Bs[r][c4*4] =
                *(const float4*)&Bm[(long long)(kt + r)*H_ + n0 + c4*4];
        }
        __syncthreads();
        #pragma unroll
        for (int kk = 0; kk < 16; kk++) {
            float a[8], b[8];
            *(float4*)&a[0] = *(float4*)&As[kk][ty*8];
            *(float4*)&a[4] = *(float4*)&As[kk][ty*8+4];
            *(float4*)&b[0] = *(float4*)&Bs[kk][tx*8];
            *(float4*)&b[4] = *(float4*)&Bs[kk][tx*8+4];
            #pragma unroll
            for (int i = 0; i < 8; i++)
                #pragma unroll
                for (int j = 0; j < 8; j++)
                    acc[i][j] += a[i] * b[j];
        }
        __syncthreads();
    }
    #pragma unroll
    for (int i = 0; i < 8; i++) {
        int m = m0 + ty*8 + i;
        if (m < live) {
            long long row = g_rowmap[m];
            float4 v0 = make_float4(acc[i][0], acc[i][1], acc[i][2], acc[i][3]);
            float4 v1 = make_float4(acc[i][4], acc[i][5], acc[i][6], acc[i][7]);
            *(float4*)&C[row*H_ + n0 + tx*8]     = v0;
            *(float4*)&C[row*H_ + n0 + tx*8 + 4] = v1;
        }
    }
}

// ---------------- M=64 split-K GEMM, 64x128 tile, 4x8 per thread ----------------
__global__ void __launch_bounds__(256) gemm_skm(
    const float* __restrict__ A, int lda,
    const float* __restrict__ Bm, int ldb,
    float* __restrict__ part, int N, int Kc)
{
    __shared__ float As[16][64];
    __shared__ float Bs[16][128];
    int n0 = blockIdx.x * 128;
    int z = blockIdx.z;
    int k0 = z * Kc;
    int tid = threadIdx.x;
    int ty = tid >> 4, tx = tid & 15;
    float acc[4][8];
    #pragma unroll
    for (int i = 0; i < 4; i++)
        #pragma unroll
        for (int j = 0; j < 8; j++) acc[i][j] = 0.0f;

    for (int kt = 0; kt < Kc; kt += 16) {
        {
            int r = tid >> 2, c4 = tid & 3;
            float4 av = *(const float4*)&A[(long long)r*lda + k0 + kt + c4*4];
            As[c4*4+0][r] = av.x; As[c4*4+1][r] = av.y;
            As[c4*4+2][r] = av.z; As[c4*4+3][r] = av.w;
        }
        #pragma unroll
        for (int i = 0; i < 2; i++) {
            int idx = tid + i*256;
            int r = idx >> 5, c4 = idx & 31;
            *(float4*)&Bs[r][c4*4] =
                *(const float4*)&Bm[(long long)(k0 + kt + r)*ldb + n0 + c4*4];
        }
        __syncthreads();
        #pragma unroll
        for (int kk = 0; kk < 16; kk++) {
            float a[4], b[8];
            *(float4*)&a[0] = *(float4*)&As[kk][ty*4];
            *(float4*)&b[0] = *(float4*)&Bs[kk][tx*8];
            *(float4*)&b[4] = *(float4*)&Bs[kk][tx*8+4];
            #pragma unroll
            for (int i = 0; i < 4; i++)
                #pragma unroll
                for (int j = 0; j < 8; j++)
                    acc[i][j] += a[i] * b[j];
        }
        __syncthreads();
    }
    float* C = part + (long long)z * 64 * N;
    #pragma unroll
    for (int i = 0; i < 4; i++) {
        int m = ty*4 + i;
        *(float4*)&C[(long long)m*N + n0 + tx*8]     = *(float4*)&acc[i][0];
        *(float4*)&C[(long long)m*N + n0 + tx*8 + 4] = *(float4*)&acc[i][4];
    }
}

// ---------------- reductions ----------------
__global__ void k_reduce_plain(const float* __restrict__ part, float* __restrict__ out,
                               int MN, int S) {
    int i = blockIdx.x*256 + threadIdx.x;
    if (i >= MN) return;
    float s = 0.f;
    for (int z = 0; z < S; z++) s += part[(long long)z*MN + i];
    out[i] = s;
}
__global__ void k_reduce_tanh(const float* __restrict__ part, float* __restrict__ out,
                              int MN, int S) {
    int i = blockIdx.x*256 + threadIdx.x;
    if (i >= MN) return;
    float s = 0.f;
    for (int z = 0; z < S; z++) s += part[(long long)z*MN + i];
    out[i] = tanhf(s);
}
__global__ void k_reduce_gen(const float* __restrict__ part, const float* __restrict__ bias,
                             int S) {
    int i = blockIdx.x*256 + threadIdx.x;
    if (i >= B_*V_) return;
    int m = i >> 13, n = i & (V_ - 1);
    float s = 0.f;
    const int MN = B_*V_;
    for (int z = 0; z < S; z++) s += part[(long long)z*MN + i];
    g_logits[m*NLOGIT + n] = (s + bias[n]) * SCALE_;
}
__global__ void k_reduce_pv(const float* __restrict__ part) {
    int i = blockIdx.x*256 + threadIdx.x;
    if (i >= 1024*H_) return;
    int m = i >> 10, n = i & (H_ - 1);
    float s = 0.f;
    const int MN = 1024*H_;
    #pragma unroll
    for (int z = 0; z < 4; z++) s += part[(long long)z*MN + i];
    int b = m / LPV_, l = m % LPV_;
    g_src[((long long)b*SLEN + LC_ + l)*H_ + n] = s;
}

// ---------------- dot products (coarse mask early-exit) ----------------
__global__ void k_dots(const float* __restrict__ Q, const float* __restrict__ Kr,
                       float* __restrict__ out, int J, int out_stride, int out_off, int mode) {
    int w = threadIdx.x >> 5, lane = threadIdx.x & 31;
    int j = blockIdx.x * 8 + w;
    int b = blockIdx.y;
    if (j >= J) return;
    float m = g_mask[b*SLEN + j];
    if (m == 0.f) {
        if (lane == 0)
            out[(long long)b*out_stride + out_off + j] = (mode == 0) ? NEGF : NEGF * SCALE_;
        return;
    }
    const float4* q4 = (const float4*)(Q + b*H_);
    const float4* k4 = (const float4*)(Kr + ((long long)b*SLEN + j)*H_);
    float s = 0.f;
    #pragma unroll
    for (int i = 0; i < 8; i++) {
        float4 qa = q4[lane + i*32];
        float4 ka = k4[lane + i*32];
        s += qa.x*ka.x + qa.y*ka.y + qa.z*ka.z + qa.w*ka.w;
    }
    #pragma unroll
    for (int o = 16; o; o >>= 1) s += __shfl_xor_sync(0xffffffffu, s, o);
    if (lane == 0)
        out[(long long)b*out_stride + out_off + j] = s * SCALE_;
}

// ---------------- row softmax ----------------
__device__ __forceinline__ float warp_red_max(float v) {
    #pragma unroll
    for (int o = 16; o; o >>= 1) v = fmaxf(v, __shfl_xor_sync(0xffffffffu, v, o));
    return v;
}
__device__ __forceinline__ float warp_red_sum(float v) {
    #pragma unroll
    for (int o = 16; o; o >>= 1) v += __shfl_xor_sync(0xffffffffu, v, o);
    return v;
}
__global__ void k_softmax(const float* __restrict__ in, long long irs,
                          float* __restrict__ out, long long ors, int n) {
    int row = blockIdx.x, tid = threadIdx.x, T = blockDim.x;
    const float* x = in + (long long)row * irs;
    float* y = out + (long long)row * ors;
    __shared__ float sh[32];
    __shared__ float stat[2];
    int lane = tid & 31, wid = tid >> 5, nw = T >> 5;

    float m = -INFINITY;
    for (int i = tid; i < n; i += T) m = fmaxf(m, x[i]);
    m = warp_red_max(m);
    if (lane == 0) sh[wid] = m;
    __syncthreads();
    if (wid == 0) {
        float vv = (lane < nw) ? sh[lane] : -INFINITY;
        vv = warp_red_max(vv);
        if (lane == 0) stat[0] = vv;
    }
    __syncthreads();
    m = stat[0];

    float s = 0.f;
    for (int i = tid; i < n; i += T) s += expf(x[i] - m);
    s = warp_red_sum(s);
    __syncthreads();
    if (lane == 0) sh[wid] = s;
    __syncthreads();
    if (wid == 0) {
        float vv = (lane < nw) ? sh[lane] : 0.f;
        vv = warp_red_sum(vv);
        if (lane == 0) stat[1] = vv;
    }
    __syncthreads();
    float inv = 1.0f / stat[1];
    for (int i = tid; i < n; i += T) y[i] = expf(x[i] - m) * inv;
}

// ---------------- per-step misc ----------------
__global__ void k_emb0(const float* __restrict__ E_topic) {
    int i = blockIdx.x*256 + threadIdx.x;
    g_emb[i] = E_topic[2*H_ + (i & (H_ - 1))];   // BOS = 2
}
// ec = emb + a @ v (no inner branch; masked a are exactly 0)
__global__ void k_ctx() {
    __shared__ float sa[SLEN];
    int b = blockIdx.y;
    int h = blockIdx.x*128 + threadIdx.x;
    for (int i = threadIdx.x; i < SLEN; i += 128) sa[i] = g_sc[b*SLEN + i];
    __syncthreads();
    const float* vb = g_v + (long long)b*SLEN*H_ + h;
    float acc = 0.f;
    #pragma unroll 4
    for (int j = 0; j < SLEN; j++) acc += sa[j] * vb[(long long)j*H_];
    g_ec[b*H_ + h] = g_emb[b*H_ + h] + acc;
}
__global__ void k_buildp(const float* __restrict__ pv_m, float* __restrict__ out1, int t) {
    int b = blockIdx.y;
    int v = blockIdx.x*256 + threadIdx.x;
    __shared__ float pv[16];
    if (threadIdx.x < 16) pv[threadIdx.x] = g_logits[b*NLOGIT + V_ + LC_ + threadIdx.x];
    __syncthreads();
    float p = g_logits[b*NLOGIT + v];
    const float* pvb = pv_m + (long long)b*LPV_*V_ + v;
    #pragma unroll
    for (int l = 0; l < 16; l++) p += pv[l] * pvb[(long long)l*V_];
    out1[(long long)b*PREF_*V_ + (long long)t*V_ + v] = p;
}
__global__ void k_scatter(const int* __restrict__ tp_path, float* __restrict__ out1, int t) {
    int b = blockIdx.x;
    int tid = threadIdx.x;
    float* dst = out1 + (long long)b*PREF_*V_ + (long long)t*V_;
    const float* pr = g_logits + b*NLOGIT;
    if (tid < 16) atomicAdd(&dst[tp_path[b*LTP_ + tid]], pr[V_ + LC_ + LPV_ + tid]);
    for (int l = tid; l < LC_; l += blockDim.x)
        atomicAdd(&dst[g_tctx[b*LC_ + l]], pr[V_ + l]);
}
// Fused gumbel + softmax over V (partitionable threefry: bits = o0^o1 of tf(key,(0,i)))
__global__ void __launch_bounds__(1024) k_gumbel_softmax(
    const float* __restrict__ out1, float* __restrict__ out2,
    int t, uint32_t kk0, uint32_t kk1)
{
    int b = blockIdx.x, tid = threadIdx.x;
    const float* p = out1 + (long long)b*PREF_*V_ + (long long)t*V_;
    float z[8];
    float m = -INFINITY;
    #pragma unroll
    for (int r = 0; r < 8; r++) {
        int v = tid + r*1024;
        uint32_t o0, o1;
        tf2x32(kk0, kk1, 0u, (uint32_t)((b << 13) + v), o0, o1);
        float zz = (logf(p[v] + 1e-10f) + gumbel_from_bits(o0 ^ o1)) / TAUF;
        z[r] = zz; m = fmaxf(m, zz);
    }
    __shared__ float sh[32];
    __shared__ float stat;
    int lane = tid & 31, wid = tid >> 5;
    m = warp_red_max(m);
    if (lane == 0) sh[wid] = m;
    __syncthreads();
    if (wid == 0) {
        float vv = warp_red_max(sh[lane]);
        if (lane == 0) stat = vv;
    }
    __syncthreads();
    m = stat;
    float s = 0.f;
    #pragma unroll
    for (int r = 0; r < 8; r++) { z[r] = expf(z[r] - m); s += z[r]; }
    s = warp_red_sum(s);
    __syncthreads();
    if (lane == 0) sh[wid] = s;
    __syncthreads();
    if (wid == 0) {
        float vv = warp_red_sum(sh[lane]);
        if (lane == 0) stat = vv;
    }
    __syncthreads();
    float inv = 1.0f / stat;
    float* y = out2 + (long long)b*PREF_*V_ + (long long)t*V_;
    #pragma unroll
    for (int r = 0; r < 8; r++) y[tid + r*1024] = z[r] * inv;
}

// ---------------- host orchestration ----------------
extern "C" void kernel_launch(void* const* d_in, const int* in_sizes, int n_in,
                              void* d_out, int out_size) {
    const int*   context     = (const int*)  d_in[0];
    const int*   context_len = (const int*)  d_in[1];
    const float* pv_m        = (const float*)d_in[2];
    const float* pv_m_mask   = (const float*)d_in[3];
    const int*   ar_gth_len  = (const int*)  d_in[5];
    const int*   tp_path     = (const int*)  d_in[6];
    const int*   tp_path_len = (const int*)  d_in[7];
    const float* tp_hidden   = (const float*)d_in[8];
    const float* ar_hidden   = (const float*)d_in[9];
    const float* E_ctx       = (const float*)d_in[10];
    const float* W_p         = (const float*)d_in[11];
    const float* E_topic     = (const float*)d_in[12];
    const float* W_q         = (const float*)d_in[13];
    const float* W_k         = (const float*)d_in[14];
    const float* W_v         = (const float*)d_in[15];
    const float* W_o         = (const float*)d_in[16];
    const float* gen_W       = (const float*)d_in[17];
    const float* gen_b       = (const float*)d_in[18];
    const int*   glo2loc     = (const int*)  d_in[19];

    float* out1 = (float*)d_out;                       // seq_gen_prob (B,16,V)
    float* out2 = out1 + (long long)B_*PREF_*V_;       // seq[:,1:]    (B,16,V)

    float *d_src, *d_k, *d_v, *d_part, *d_emb, *d_q, *d_ec, *d_dec, *d_sc, *d_logits;
    cudaGetSymbolAddress((void**)&d_src,    g_src);
    cudaGetSymbolAddress((void**)&d_k,      g_k);
    cudaGetSymbolAddress((void**)&d_v,      g_v);
    cudaGetSymbolAddress((void**)&d_part,   g_part);
    cudaGetSymbolAddress((void**)&d_emb,    g_emb);
    cudaGetSymbolAddress((void**)&d_q,      g_q);
    cudaGetSymbolAddress((void**)&d_ec,     g_ec);
    cudaGetSymbolAddress((void**)&d_dec,    g_dec);
    cudaGetSymbolAddress((void**)&d_sc,     g_sc);
    cudaGetSymbolAddress((void**)&d_logits, g_logits);

    const int M_src = B_*SLEN;           // 34880
    const int MTILES = (M_src + 127)/128; // 273

    // ---- precompute ----
    k_build_src<<<(B_*SLEN*H_)/256, 256>>>(context, context_len, tp_hidden, ar_hidden, E_ctx);
    k_mask<<<(B_*SLEN + 255)/256, 256>>>(context_len, pv_m_mask, tp_path_len, ar_gth_len);
    k_tctx<<<(B_*LC_)/256, 256>>>(context, glo2loc);
    k_rowmap<<<1, 64>>>(context_len);

    // pv_hidden = pv_m (1024x8192) @ W_p (8192x1024), split-K=4
    gemm_big<<<dim3(8, 8, 4), 256>>>(pv_m, V_, W_p, H_, d_part, 1024, H_, V_/4);
    k_reduce_pv<<<(1024*H_)/256, 256>>>(d_part);

    // k, v over compacted live rows only
    gemm_gather<<<dim3(8, MTILES), 256>>>(d_src, W_k, d_k);
    gemm_gather<<<dim3(8, MTILES), 256>>>(d_src, W_v, d_v);

    // ---- autoregressive steps ----
    for (int t = 0; t < PREF_; t++) {
        // emb
        if (t == 0) {
            k_emb0<<<(B_*H_)/256, 256>>>(E_topic);
        } else {
            gemm_skm<<<dim3(H_/128, 1, 16), 256>>>(out2 + (long long)(t-1)*V_, PREF_*V_,
                                                   E_topic, H_, d_part, H_, V_/16);
            k_reduce_plain<<<(B_*H_)/256, 256>>>(d_part, d_emb, B_*H_, 16);
        }
        // q = emb @ W_q
        gemm_skm<<<dim3(H_/128, 1, 8), 256>>>(d_emb, H_, W_q, H_, d_part, H_, H_/8);
        k_reduce_plain<<<(B_*H_)/256, 256>>>(d_part, d_q, B_*H_, 8);
        // attention scores + softmax
        k_dots<<<dim3((SLEN + 7)/8, B_), 256>>>(d_q, d_k, d_sc, SLEN, SLEN, 0, 0);
        k_softmax<<<B_, 256>>>(d_sc, SLEN, d_sc, SLEN, SLEN);
        // ec = emb + a @ v
        k_ctx<<<dim3(H_/128, B_), 128>>>();
        // dec = tanh(ec @ W_o)
        gemm_skm<<<dim3(H_/128, 1, 8), 256>>>(d_ec, H_, W_o, H_, d_part, H_, H_/8);
        k_reduce_tanh<<<(B_*H_)/256, 256>>>(d_part, d_dec, B_*H_, 8);
        // gen logits
        gemm_skm<<<dim3(V_/128, 1, 2), 256>>>(d_dec, H_, gen_W, V_, d_part, V_, H_/2);
        k_reduce_gen<<<(B_*V_)/256, 256>>>(d_part, gen_b, 2);
        // copy logits
        k_dots<<<dim3((SLEN-1 + 7)/8, B_), 256>>>(d_dec, d_src, d_logits, SLEN-1, NLOGIT, V_, 1);
        // softmax over 8736
        k_softmax<<<B_, 512>>>(d_logits, NLOGIT, d_logits, NLOGIT, NLOGIT);
        // p = gen + pv mixture, then scatter tp/ctx
        k_buildp<<<dim3(V_/256, B_), 256>>>(pv_m, out1, t);
        k_scatter<<<B_, 256>>>(tp_path, out1, t);
        // gumbel + y softmax (fused)
        uint32_t kk0, kk1;
        tf2x32(0u, 42u, 0u, (uint32_t)t, kk0, kk1);
        k_gumbel_softmax<<<B_, 1024>>>(out1, out2, t, kk0, kk1);
    }
    (void)in_sizes; (void)n_in; (void)out_size;
}

// round 17
// speedup vs baseline: 1.3019x; 1.1864x over previous
#include <cuda_runtime.h>
#include <cuda_bf16.h>
#include <math.h>
#include <stdint.h>

#define B_    64
#define LC_   512
#define LPV_  16
#define LTP_  16
#define V_    8192
#define H_    1024
#define SLEN  545
#define NLOGIT 8736
#define PREF_ 16
#define NEGF  (-1000000000.0f)
#define SCALE_ 0.03125f
#define TAUF  0.67f

// ---------------- scratch ----------------
__device__ float g_src [B_*SLEN*H_];
__device__ float g_k   [B_*SLEN*H_];
__device__ float g_v   [B_*SLEN*H_];
__device__ float g_mask[B_*SLEN];
__device__ int   g_tctx[B_*LC_];
__device__ float g_emb [B_*H_];
__device__ float g_q   [B_*H_];
__device__ float g_ec  [B_*H_];
__device__ float g_dec [B_*H_];
__device__ float g_sc  [B_*SLEN];
__device__ float g_logits[B_*NLOGIT];
__device__ float g_part[4*1024*1024];
__device__ int   g_rowmap[B_*SLEN + 128];
__device__ int   g_live;
// bf16 operands
__device__ __nv_bfloat16 g_srcb[B_*SLEN*H_];
__device__ __nv_bfloat16 g_wkb [H_*H_];
__device__ __nv_bfloat16 g_wvb [H_*H_];
__device__ __nv_bfloat16 g_pvmb[B_*LPV_*V_];
__device__ __nv_bfloat16 g_wpb [V_*H_];

// ---------------- threefry2x32 (exact JAX semantics) ----------------
__host__ __device__ __forceinline__ void tf2x32(uint32_t k0, uint32_t k1,
                                                uint32_t x0, uint32_t x1,
                                                uint32_t& o0, uint32_t& o1) {
    uint32_t k2 = k0 ^ k1 ^ 0x1BD11BDAu;
#define RND_(r) { x0 += x1; x1 = (x1 << r) | (x1 >> (32 - r)); x1 ^= x0; }
    x0 += k0; x1 += k1;
    RND_(13) RND_(15) RND_(26) RND_(6)   x0 += k1; x1 += k2 + 1u;
    RND_(17) RND_(29) RND_(16) RND_(24)  x0 += k2; x1 += k0 + 2u;
    RND_(13) RND_(15) RND_(26) RND_(6)   x0 += k0; x1 += k1 + 3u;
    RND_(17) RND_(29) RND_(16) RND_(24)  x0 += k1; x1 += k2 + 4u;
    RND_(13) RND_(15) RND_(26) RND_(6)   x0 += k2; x1 += k0 + 5u;
#undef RND_
    o0 = x0; o1 = x1;
}

__device__ __forceinline__ float gumbel_from_bits(uint32_t w) {
    float f = __uint_as_float((w >> 9) | 0x3f800000u) - 1.0f;
    float u = fmaxf(1e-10f, f + 1e-10f);
    return -logf(-logf(u));
}

// ---------------- setup kernels ----------------
__global__ void k_build_src(const int* __restrict__ context, const int* __restrict__ ctxlen,
                            const float* __restrict__ tp_hidden, const float* __restrict__ ar_hidden,
                            const float* __restrict__ E_ctx) {
    int idx = blockIdx.x * 256 + threadIdx.x;
    int h = idx & (H_ - 1);
    int r = idx >> 10;
    int j = r % SLEN;
    int b = r / SLEN;
    float val;
    if (j < LC_) {
        val = (j < ctxlen[b]) ? E_ctx[(long long)context[b*LC_ + j] * H_ + h] : 0.0f;
    } else if (j < LC_ + LPV_) {
        return;  // filled by pv mma
    } else if (j < LC_ + LPV_ + LTP_) {
        val = tp_hidden[((long long)b*LTP_ + (j - (LC_+LPV_)))*H_ + h];
    } else {
        val = ar_hidden[b*H_ + h];
    }
    g_src[idx] = val;
}

__global__ void k_mask(const int* __restrict__ ctxlen, const float* __restrict__ pvmask,
                       const int* __restrict__ tplen, const int* __restrict__ arlen) {
    int i = blockIdx.x * 256 + threadIdx.x;
    if (i >= B_*SLEN) return;
    int b = i / SLEN, j = i % SLEN;
    float m;
    if (j < LC_)                m = (j < ctxlen[b]) ? 1.0f : 0.0f;
    else if (j < LC_+LPV_)      m = pvmask[b*LPV_ + (j - LC_)];
    else if (j < LC_+LPV_+LTP_) m = ((j - (LC_+LPV_)) < tplen[b]) ? 1.0f : 0.0f;
    else                        m = (0 < arlen[b]) ? 1.0f : 0.0f;
    g_mask[i] = m;
}

__global__ void k_tctx(const int* __restrict__ context, const int* __restrict__ glo2loc) {
    int i = blockIdx.x * 256 + threadIdx.x;
    if (i >= B_*LC_) return;
    g_tctx[i] = glo2loc[context[i]];
}

__global__ void k_rowmap(const int* __restrict__ ctxlen) {
    __shared__ int offs[65];
    int tid = threadIdx.x;
    if (tid == 0) {
        int acc = 0;
        for (int i = 0; i < 64; i++) { offs[i] = acc; acc += ctxlen[i] + (SLEN - LC_); }
        offs[64] = acc;
    }
    __syncthreads();
    int b = tid;
    int o = offs[b], c = ctxlen[b];
    for (int j = 0; j < c; j++)            g_rowmap[o + j] = b*SLEN + j;
    for (int j = 0; j < SLEN - LC_; j++)   g_rowmap[o + c + j] = b*SLEN + LC_ + j;
    __syncthreads();
    if (tid == 0) {
        int L = offs[64];
        int P = (L + 127) & ~127;
        for (int i = L; i < P; i++) g_rowmap[i] = 0;
        g_live = L;
    }
}

// float -> bf16 conversion (pairwise)
__global__ void k_cvt2(const float2* __restrict__ in, __nv_bfloat162* __restrict__ out, int n2) {
    int i = blockIdx.x*256 + threadIdx.x;
    if (i < n2) {
        float2 v = in[i];
        out[i] = __floats2bfloat162_rn(v.x, v.y);
    }
}

// ---------------- bf16 tensor-core GEMM ----------------
// C[out_row(m)][n] = sum_k A[in_row(m)][k] * B[k][n]
// Block: 256 thr = 8 warps (4 x 2). Block tile 128(M) x 64(N). k-chunk 32.
// mma.sync m16n8k16 row.col f32.bf16.bf16.f32, fragments per PTX ISA table.
__global__ void __launch_bounds__(256) mma_gemm(
    const __nv_bfloat16* __restrict__ A,
    const __nv_bfloat16* __restrict__ B0,
    const __nv_bfloat16* __restrict__ B1,
    float* __restrict__ C0, float* __restrict__ C1,
    int K, int N, int Mp, int use_rowmap, int pv_scatter)
{
    int M = (Mp < 0) ? g_live : Mp;
    int m0 = blockIdx.y * 128;
    if (m0 >= M) return;
    int n0 = blockIdx.x * 64;
    const __nv_bfloat16* Bm = blockIdx.z ? B1 : B0;
    float* C = blockIdx.z ? C1 : C0;

    __shared__ __nv_bfloat16 As[128][40];
    __shared__ __nv_bfloat16 Bs[64][40];

    int tid = threadIdx.x;
    int wid = tid >> 5, lane = tid & 31;
    int warp_m = wid & 3, warp_n = wid >> 2;
    int g = lane >> 2, cq = lane & 3;

    // A loading: 2 threads per row, uint4 (16 bf16) each x2
    int ar = tid >> 1;
    int apart = tid & 1;
    long long arow = use_rowmap ? (long long)g_rowmap[m0 + ar] : (long long)(m0 + ar);
    const uint4* aptr = (const uint4*)(A + arow * (long long)K);

    float acc[2][4][4];
    #pragma unroll
    for (int am = 0; am < 2; am++)
        #pragma unroll
        for (int bn = 0; bn < 4; bn++)
            #pragma unroll
            for (int r = 0; r < 4; r++) acc[am][bn][r] = 0.0f;

    for (int kt = 0; kt < K; kt += 32) {
        // A tile: rows 0..127, k kt..kt+31
        uint4 av0 = aptr[(kt >> 3) + apart*2];
        uint4 av1 = aptr[(kt >> 3) + apart*2 + 1];
        *(uint4*)&As[ar][apart*16]     = av0;
        *(uint4*)&As[ar][apart*16 + 8] = av1;
        // B tile transposed: Bs[n][k]
        #pragma unroll
        for (int i = 0; i < 4; i++) {
            int u = tid + i*256;        // 0..1023
            int k = u >> 5;             // 0..31
            int np = u & 31;            // n-pair
            uint32_t w = *(const uint32_t*)(Bm + (long long)(kt + k)*N + n0 + np*2);
            __nv_bfloat162 p = *(__nv_bfloat162*)&w;
            Bs[np*2][k]     = p.x;
            Bs[np*2 + 1][k] = p.y;
        }
        __syncthreads();
        #pragma unroll
        for (int ks = 0; ks < 32; ks += 16) {
            uint32_t a[2][4];
            #pragma unroll
            for (int am = 0; am < 2; am++) {
                int rb = warp_m*32 + am*16;
                a[am][0] = *(const uint32_t*)&As[rb + g][ks + 2*cq];
                a[am][1] = *(const uint32_t*)&As[rb + g + 8][ks + 2*cq];
                a[am][2] = *(const uint32_t*)&As[rb + g][ks + 2*cq + 8];
                a[am][3] = *(const uint32_t*)&As[rb + g + 8][ks + 2*cq + 8];
            }
            uint32_t b[4][2];
            #pragma unroll
            for (int bn = 0; bn < 4; bn++) {
                int n = warp_n*32 + bn*8 + g;
                b[bn][0] = *(const uint32_t*)&Bs[n][ks + 2*cq];
                b[bn][1] = *(const uint32_t*)&Bs[n][ks + 2*cq + 8];
            }
            #pragma unroll
            for (int am = 0; am < 2; am++)
                #pragma unroll
                for (int bn = 0; bn < 4; bn++) {
                    asm volatile(
                        "mma.sync.aligned.m16n8k16.row.col.f32.bf16.bf16.f32 "
                        "{%0,%1,%2,%3}, {%4,%5,%6,%7}, {%8,%9}, {%0,%1,%2,%3};\n"
                        : "+f"(acc[am][bn][0]), "+f"(acc[am][bn][1]),
                          "+f"(acc[am][bn][2]), "+f"(acc[am][bn][3])
                        : "r"(a[am][0]), "r"(a[am][1]), "r"(a[am][2]), "r"(a[am][3]),
                          "r"(b[bn][0]), "r"(b[bn][1]));
                }
        }
        __syncthreads();
    }

    // epilogue: c0,c1 -> (row g, col 2c,2c+1); c2,c3 -> (row g+8)
    #pragma unroll
    for (int am = 0; am < 2; am++) {
        #pragma unroll
        for (int bn = 0; bn < 4; bn++) {
            int mrow0 = m0 + warp_m*32 + am*16 + g;
            int col   = n0 + warp_n*32 + bn*8 + 2*cq;
            if (mrow0 < M) {
                long long orow = use_rowmap ? (long long)g_rowmap[mrow0]
                               : pv_scatter ? (long long)((mrow0 >> 4)*SLEN + LC_ + (mrow0 & 15))
                               : (long long)mrow0;
                float2 v = make_float2(acc[am][bn][0], acc[am][bn][1]);
                *(float2*)&C[orow*H_ + col] = v;
            }
            int mrow1 = mrow0 + 8;
            if (mrow1 < M) {
                long long orow = use_rowmap ? (long long)g_rowmap[mrow1]
                               : pv_scatter ? (long long)((mrow1 >> 4)*SLEN + LC_ + (mrow1 & 15))
                               : (long long)mrow1;
                float2 v = make_float2(acc[am][bn][2], acc[am][bn][3]);
                *(float2*)&C[orow*H_ + col] = v;
            }
        }
    }
}

// ---------------- M=64 split-K GEMM, 64x128 tile, 4x8 per thread ----------------
__global__ void __launch_bounds__(256) gemm_skm(
    const float* __restrict__ A, int lda,
    const float* __restrict__ Bm, int ldb,
    float* __restrict__ part, int N, int Kc)
{
    __shared__ float As[16][64];
    __shared__ float Bs[16][128];
    int n0 = blockIdx.x * 128;
    int z = blockIdx.z;
    int k0 = z * Kc;
    int tid = threadIdx.x;
    int ty = tid >> 4, tx = tid & 15;
    float acc[4][8];
    #pragma unroll
    for (int i = 0; i < 4; i++)
        #pragma unroll
        for (int j = 0; j < 8; j++) acc[i][j] = 0.0f;

    for (int kt = 0; kt < Kc; kt += 16) {
        {
            int r = tid >> 2, c4 = tid & 3;
            float4 av = *(const float4*)&A[(long long)r*lda + k0 + kt + c4*4];
            As[c4*4+0][r] = av.x; As[c4*4+1][r] = av.y;
            As[c4*4+2][r] = av.z; As[c4*4+3][r] = av.w;
        }
        #pragma unroll
        for (int i = 0; i < 2; i++) {
            int idx = tid + i*256;
            int r = idx >> 5, c4 = idx & 31;
            *(float4*)&Bs[r][c4*4] =
                *(const float4*)&Bm[(long long)(k0 + kt + r)*ldb + n0 + c4*4];
        }
        __syncthreads();
        #pragma unroll
        for (int kk = 0; kk < 16; kk++) {
            float a[4], b[8];
            *(float4*)&a[0] = *(float4*)&As[kk][ty*4];
            *(float4*)&b[0] = *(float4*)&Bs[kk][tx*8];
            *(float4*)&b[4] = *(float4*)&Bs[kk][tx*8+4];
            #pragma unroll
            for (int i = 0; i < 4; i++)
                #pragma unroll
                for (int j = 0; j < 8; j++)
                    acc[i][j] += a[i] * b[j];
        }
        __syncthreads();
    }
    float* C = part + (long long)z * 64 * N;
    #pragma unroll
    for (int i = 0; i < 4; i++) {
        int m = ty*4 + i;
        *(float4*)&C[(long long)m*N + n0 + tx*8]     = *(float4*)&acc[i][0];
        *(float4*)&C[(long long)m*N + n0 + tx*8 + 4] = *(float4*)&acc[i][4];
    }
}

// ---------------- reductions ----------------
__global__ void k_reduce_plain(const float* __restrict__ part, float* __restrict__ out,
                               int MN, int S) {
    int i = blockIdx.x*256 + threadIdx.x;
    if (i >= MN) return;
    float s = 0.f;
    for (int z = 0; z < S; z++) s += part[(long long)z*MN + i];
    out[i] = s;
}
__global__ void k_reduce_tanh(const float* __restrict__ part, float* __restrict__ out,
                              int MN, int S) {
    int i = blockIdx.x*256 + threadIdx.x;
    if (i >= MN) return;
    float s = 0.f;
    for (int z = 0; z < S; z++) s += part[(long long)z*MN + i];
    out[i] = tanhf(s);
}
__global__ void k_reduce_gen(const float* __restrict__ part, const float* __restrict__ bias,
                             int S) {
    int i = blockIdx.x*256 + threadIdx.x;
    if (i >= B_*V_) return;
    int m = i >> 13, n = i & (V_ - 1);
    float s = 0.f;
    const int MN = B_*V_;
    for (int z = 0; z < S; z++) s += part[(long long)z*MN + i];
    g_logits[m*NLOGIT + n] = (s + bias[n]) * SCALE_;
}

// ---------------- dot products (coarse mask early-exit) ----------------
__global__ void k_dots(const float* __restrict__ Q, const float* __restrict__ Kr,
                       float* __restrict__ out, int J, int out_stride, int out_off, int mode) {
    int w = threadIdx.x >> 5, lane = threadIdx.x & 31;
    int j = blockIdx.x * 8 + w;
    int b = blockIdx.y;
    if (j >= J) return;
    float m = g_mask[b*SLEN + j];
    if (m == 0.f) {
        if (lane == 0)
            out[(long long)b*out_stride + out_off + j] = (mode == 0) ? NEGF : NEGF * SCALE_;
        return;
    }
    const float4* q4 = (const float4*)(Q + b*H_);
    const float4* k4 = (const float4*)(Kr + ((long long)b*SLEN + j)*H_);
    float s = 0.f;
    #pragma unroll
    for (int i = 0; i < 8; i++) {
        float4 qa = q4[lane + i*32];
        float4 ka = k4[lane + i*32];
        s += qa.x*ka.x + qa.y*ka.y + qa.z*ka.z + qa.w*ka.w;
    }
    #pragma unroll
    for (int o = 16; o; o >>= 1) s += __shfl_xor_sync(0xffffffffu, s, o);
    if (lane == 0)
        out[(long long)b*out_stride + out_off + j] = s * SCALE_;
}

// ---------------- reductions helpers ----------------
__device__ __forceinline__ float warp_red_max(float v) {
    #pragma unroll
    for (int o = 16; o; o >>= 1) v = fmaxf(v, __shfl_xor_sync(0xffffffffu, v, o));
    return v;
}
__device__ __forceinline__ float warp_red_sum(float v) {
    #pragma unroll
    for (int o = 16; o; o >>= 1) v += __shfl_xor_sync(0xffffffffu, v, o);
    return v;
}
__global__ void k_softmax(const float* __restrict__ in, long long irs,
                          float* __restrict__ out, long long ors, int n) {
    int row = blockIdx.x, tid = threadIdx.x, T = blockDim.x;
    const float* x = in + (long long)row * irs;
    float* y = out + (long long)row * ors;
    __shared__ float sh[32];
    __shared__ float stat[2];
    int lane = tid & 31, wid = tid >> 5, nw = T >> 5;

    float m = -INFINITY;
    for (int i = tid; i < n; i += T) m = fmaxf(m, x[i]);
    m = warp_red_max(m);
    if (lane == 0) sh[wid] = m;
    __syncthreads();
    if (wid == 0) {
        float vv = (lane < nw) ? sh[lane] : -INFINITY;
        vv = warp_red_max(vv);
        if (lane == 0) stat[0] = vv;
    }
    __syncthreads();
    m = stat[0];

    float s = 0.f;
    for (int i = tid; i < n; i += T) s += expf(x[i] - m);
    s = warp_red_sum(s);
    __syncthreads();
    if (lane == 0) sh[wid] = s;
    __syncthreads();
    if (wid == 0) {
        float vv = (lane < nw) ? sh[lane] : 0.f;
        vv = warp_red_sum(vv);
        if (lane == 0) stat[1] = vv;
    }
    __syncthreads();
    float inv = 1.0f / stat[1];
    for (int i = tid; i < n; i += T) y[i] = expf(x[i] - m) * inv;
}

// ---------------- per-step misc ----------------
__global__ void k_emb0(const float* __restrict__ E_topic) {
    int i = blockIdx.x*256 + threadIdx.x;
    g_emb[i] = E_topic[2*H_ + (i & (H_ - 1))];   // BOS = 2
}
// fused: softmax(sc) in-block, then ec = emb + a @ v
__global__ void k_ctx() {
    __shared__ float sa[SLEN];
    __shared__ float w4[4];
    __shared__ float red[2];
    int b = blockIdx.y;
    int tid = threadIdx.x;
    int lane = tid & 31, wid = tid >> 5;
    for (int i = tid; i < SLEN; i += 128) sa[i] = g_sc[b*SLEN + i];
    __syncthreads();
    float m = -INFINITY;
    for (int i = tid; i < SLEN; i += 128) m = fmaxf(m, sa[i]);
    m = warp_red_max(m);
    if (lane == 0) w4[wid] = m;
    __syncthreads();
    if (tid == 0) red[0] = fmaxf(fmaxf(w4[0], w4[1]), fmaxf(w4[2], w4[3]));
    __syncthreads();
    m = red[0];
    float s = 0.f;
    for (int i = tid; i < SLEN; i += 128) { float e = expf(sa[i] - m); sa[i] = e; s += e; }
    s = warp_red_sum(s);
    if (lane == 0) w4[wid] = s;
    __syncthreads();
    if (tid == 0) red[1] = w4[0] + w4[1] + w4[2] + w4[3];
    __syncthreads();
    float inv = 1.0f / red[1];
    int h = blockIdx.x*128 + tid;
    const float* vb = g_v + (long long)b*SLEN*H_ + h;
    float acc = 0.f;
    #pragma unroll 4
    for (int j = 0; j < SLEN; j++) acc += sa[j] * vb[(long long)j*H_];
    g_ec[b*H_ + h] = g_emb[b*H_ + h] + acc * inv;
}
__global__ void k_buildp(const float* __restrict__ pv_m, float* __restrict__ out1, int t) {
    int b = blockIdx.y;
    int v = blockIdx.x*256 + threadIdx.x;
    __shared__ float pv[16];
    if (threadIdx.x < 16) pv[threadIdx.x] = g_logits[b*NLOGIT + V_ + LC_ + threadIdx.x];
    __syncthreads();
    float p = g_logits[b*NLOGIT + v];
    const float* pvb = pv_m + (long long)b*LPV_*V_ + v;
    #pragma unroll
    for (int l = 0; l < 16; l++) p += pv[l] * pvb[(long long)l*V_];
    out1[(long long)b*PREF_*V_ + (long long)t*V_ + v] = p;
}
__global__ void k_scatter(const int* __restrict__ tp_path, float* __restrict__ out1, int t) {
    int b = blockIdx.x;
    int tid = threadIdx.x;
    float* dst = out1 + (long long)b*PREF_*V_ + (long long)t*V_;
    const float* pr = g_logits + b*NLOGIT;
    if (tid < 16) atomicAdd(&dst[tp_path[b*LTP_ + tid]], pr[V_ + LC_ + LPV_ + tid]);
    for (int l = tid; l < LC_; l += blockDim.x)
        atomicAdd(&dst[g_tctx[b*LC_ + l]], pr[V_ + l]);
}
__global__ void __launch_bounds__(1024) k_gumbel_softmax(
    const float* __restrict__ out1, float* __restrict__ out2,
    int t, uint32_t kk0, uint32_t kk1)
{
    int b = blockIdx.x, tid = threadIdx.x;
    const float* p = out1 + (long long)b*PREF_*V_ + (long long)t*V_;
    float z[8];
    float m = -INFINITY;
    #pragma unroll
    for (int r = 0; r < 8; r++) {
        int v = tid + r*1024;
        uint32_t o0, o1;
        tf2x32(kk0, kk1, 0u, (uint32_t)((b << 13) + v), o0, o1);
        float zz = (logf(p[v] + 1e-10f) + gumbel_from_bits(o0 ^ o1)) / TAUF;
        z[r] = zz; m = fmaxf(m, zz);
    }
    __shared__ float sh[32];
    __shared__ float stat;
    int lane = tid & 31, wid = tid >> 5;
    m = warp_red_max(m);
    if (lane == 0) sh[wid] = m;
    __syncthreads();
    if (wid == 0) {
        float vv = warp_red_max(sh[lane]);
        if (lane == 0) stat = vv;
    }
    __syncthreads();
    m = stat;
    float s = 0.f;
    #pragma unroll
    for (int r = 0; r < 8; r++) { z[r] = expf(z[r] - m); s += z[r]; }
    s = warp_red_sum(s);
    __syncthreads();
    if (lane == 0) sh[wid] = s;
    __syncthreads();
    if (wid == 0) {
        float vv = warp_red_sum(sh[lane]);
        if (lane == 0) stat = vv;
    }
    __syncthreads();
    float inv = 1.0f / stat;
    float* y = out2 + (long long)b*PREF_*V_ + (long long)t*V_;
    #pragma unroll
    for (int r = 0; r < 8; r++) y[tid + r*1024] = z[r] * inv;
}

// ---------------- host orchestration ----------------
extern "C" void kernel_launch(void* const* d_in, const int* in_sizes, int n_in,
                              void* d_out, int out_size) {
    const int*   context     = (const int*)  d_in[0];
    const int*   context_len = (const int*)  d_in[1];
    const float* pv_m        = (const float*)d_in[2];
    const float* pv_m_mask   = (const float*)d_in[3];
    const int*   ar_gth_len  = (const int*)  d_in[5];
    const int*   tp_path     = (const int*)  d_in[6];
    const int*   tp_path_len = (const int*)  d_in[7];
    const float* tp_hidden   = (const float*)d_in[8];
    const float* ar_hidden   = (const float*)d_in[9];
    const float* E_ctx       = (const float*)d_in[10];
    const float* W_p         = (const float*)d_in[11];
    const float* E_topic     = (const float*)d_in[12];
    const float* W_q         = (const float*)d_in[13];
    const float* W_k         = (const float*)d_in[14];
    const float* W_v         = (const float*)d_in[15];
    const float* W_o         = (const float*)d_in[16];
    const float* gen_W       = (const float*)d_in[17];
    const float* gen_b       = (const float*)d_in[18];
    const int*   glo2loc     = (const int*)  d_in[19];

    float* out1 = (float*)d_out;                       // seq_gen_prob (B,16,V)
    float* out2 = out1 + (long long)B_*PREF_*V_;       // seq[:,1:]    (B,16,V)

    float *d_src, *d_k, *d_v, *d_part, *d_emb, *d_q, *d_ec, *d_dec, *d_sc, *d_logits;
    __nv_bfloat16 *d_srcb, *d_wkb, *d_wvb, *d_pvmb, *d_wpb;
    cudaGetSymbolAddress((void**)&d_src,    g_src);
    cudaGetSymbolAddress((void**)&d_k,      g_k);
    cudaGetSymbolAddress((void**)&d_v,      g_v);
    cudaGetSymbolAddress((void**)&d_part,   g_part);
    cudaGetSymbolAddress((void**)&d_emb,    g_emb);
    cudaGetSymbolAddress((void**)&d_q,      g_q);
    cudaGetSymbolAddress((void**)&d_ec,     g_ec);
    cudaGetSymbolAddress((void**)&d_dec,    g_dec);
    cudaGetSymbolAddress((void**)&d_sc,     g_sc);
    cudaGetSymbolAddress((void**)&d_logits, g_logits);
    cudaGetSymbolAddress((void**)&d_srcb,   g_srcb);
    cudaGetSymbolAddress((void**)&d_wkb,    g_wkb);
    cudaGetSymbolAddress((void**)&d_wvb,    g_wvb);
    cudaGetSymbolAddress((void**)&d_pvmb,   g_pvmb);
    cudaGetSymbolAddress((void**)&d_wpb,    g_wpb);

    const int M_src = B_*SLEN;            // 34880
    const int MTILES = (M_src + 127)/128; // 273

    // ---- precompute ----
    k_build_src<<<(B_*SLEN*H_)/256, 256>>>(context, context_len, tp_hidden, ar_hidden, E_ctx);
    k_mask<<<(B_*SLEN + 255)/256, 256>>>(context_len, pv_m_mask, tp_path_len, ar_gth_len);
    k_tctx<<<(B_*LC_)/256, 256>>>(context, glo2loc);
    k_rowmap<<<1, 64>>>(context_len);

    // bf16 conversions
    k_cvt2<<<(B_*LPV_*V_/2 + 255)/256, 256>>>((const float2*)pv_m, (__nv_bfloat162*)d_pvmb, B_*LPV_*V_/2);
    k_cvt2<<<(V_*H_/2 + 255)/256, 256>>>((const float2*)W_p, (__nv_bfloat162*)d_wpb, V_*H_/2);
    k_cvt2<<<(H_*H_/2 + 255)/256, 256>>>((const float2*)W_k, (__nv_bfloat162*)d_wkb, H_*H_/2);
    k_cvt2<<<(H_*H_/2 + 255)/256, 256>>>((const float2*)W_v, (__nv_bfloat162*)d_wvb, H_*H_/2);

    // pv_hidden = pv_m @ W_p  (1024 x 1024, K=8192), scatter into g_src pv rows
    mma_gemm<<<dim3(16, 8, 1), 256>>>(d_pvmb, d_wpb, d_wpb, d_src, d_src,
                                      V_, H_, 1024, 0, 1);
    // src -> bf16 (after pv rows are in place)
    k_cvt2<<<(B_*SLEN*H_/2 + 255)/256, 256>>>((const float2*)d_src, (__nv_bfloat162*)d_srcb, B_*SLEN*H_/2);

    // k, v = src @ W_k / W_v over compacted live rows (one launch, z selects weight)
    mma_gemm<<<dim3(16, MTILES, 2), 256>>>(d_srcb, d_wkb, d_wvb, d_k, d_v,
                                           H_, H_, -1, 1, 0);

    // ---- autoregressive steps ----
    for (int t = 0; t < PREF_; t++) {
        if (t == 0) {
            k_emb0<<<(B_*H_)/256, 256>>>(E_topic);
        } else {
            gemm_skm<<<dim3(H_/128, 1, 16), 256>>>(out2 + (long long)(t-1)*V_, PREF_*V_,
                                                   E_topic, H_, d_part, H_, V_/16);
            k_reduce_plain<<<(B_*H_)/256, 256>>>(d_part, d_emb, B_*H_, 16);
        }
        gemm_skm<<<dim3(H_/128, 1, 8), 256>>>(d_emb, H_, W_q, H_, d_part, H_, H_/8);
        k_reduce_plain<<<(B_*H_)/256, 256>>>(d_part, d_q, B_*H_, 8);
        k_dots<<<dim3((SLEN + 7)/8, B_), 256>>>(d_q, d_k, d_sc, SLEN, SLEN, 0, 0);
        k_ctx<<<dim3(H_/128, B_), 128>>>();
        gemm_skm<<<dim3(H_/128, 1, 8), 256>>>(d_ec, H_, W_o, H_, d_part, H_, H_/8);
        k_reduce_tanh<<<(B_*H_)/256, 256>>>(d_part, d_dec, B_*H_, 8);
        gemm_skm<<<dim3(V_/128, 1, 2), 256>>>(d_dec, H_, gen_W, V_, d_part, V_, H_/2);
        k_reduce_gen<<<(B_*V_)/256, 256>>>(d_part, gen_b, 2);
        k_dots<<<dim3((SLEN-1 + 7)/8, B_), 256>>>(d_dec, d_src, d_logits, SLEN-1, NLOGIT, V_, 1);
        k_softmax<<<B_, 512>>>(d_logits, NLOGIT, d_logits, NLOGIT, NLOGIT);
        k_buildp<<<dim3(V_/256, B_), 256>>>(pv_m, out1, t);
        k_scatter<<<B_, 256>>>(tp_path, out1, t);
        uint32_t kk0, kk1;
        tf2x32(0u, 42u, 0u, (uint32_t)t, kk0, kk1);
        k_gumbel_softmax<<<B_, 1024>>>(out1, out2, t, kk0, kk1);
    }
    (void)in_sizes; (void)n_in; (void)out_size;
}